// round 11
// baseline (speedup 1.0000x reference)
#include <cuda_runtime.h>
#include <math.h>

#define BB 32
#define SS 1024
#define NTOK (BB*SS)      // 32768 tokens
#define HH 32
#define WW 32
#define HWB (HH*WW)       // 1024 bins
#define P2 256
#define CC 3
#define DD (CC*P2)        // 768
#define MAXB 192
#define EPSV 1e-6f

// ---- scratch (device globals; no allocation) ----
__device__ int g_bincount[HWB];
__device__ int g_binlist[HWB * MAXB];   // 768 KB

// ---------------------------------------------------------------------------
// K0: zero bin counters (graph replays -> must reset every launch)
// ---------------------------------------------------------------------------
__global__ void k_zero() {
    int i = blockIdx.x * blockDim.x + threadIdx.x;
    if (i < HWB) g_bincount[i] = 0;
}

// ---------------------------------------------------------------------------
// K1: bin valid tokens by flat grid index pf (mask is int32; nonzero = pad)
// ---------------------------------------------------------------------------
__global__ void k_bin(const int* __restrict__ pos_h,
                      const int* __restrict__ pos_w,
                      const int* __restrict__ mask) {
    int t = blockIdx.x * blockDim.x + threadIdx.x;
    if (t >= NTOK) return;
    if (mask[t] != 0) return;
    int pf = pos_h[t] * WW + pos_w[t];
    int idx = atomicAdd(&g_bincount[pf], 1);
    if (idx < MAXB) g_binlist[pf * MAXB + idx] = t;
}

// ---------------------------------------------------------------------------
// K2: zero output rows of masked (padded) tokens. 64 lanes per token.
// ---------------------------------------------------------------------------
__global__ void __launch_bounds__(256) k_maskzero(const int* __restrict__ mask,
                                                  float* __restrict__ out) {
    int t = blockIdx.x * 4 + (threadIdx.x >> 6);
    int lane = threadIdx.x & 63;
    if (mask[t] == 0) return;
    float4* orow = (float4*)(out + (size_t)t * DD);
    float4 z = make_float4(0.f, 0.f, 0.f, 0.f);
    __stcs(&orow[lane], z);
    __stcs(&orow[lane + 64], z);
    __stcs(&orow[lane + 128], z);
}

// ---------------------------------------------------------------------------
// K3: FUSED per-bin stats + normalize. One 512-thread block per bin.
//   Phase A (stats): two 256-thread halves sum alternate tokens
//     a = xbar - mean_old ; S1 = sum a ; S2 = sum a^2   (plain loads -> L2)
//     mean_new = mo + S1/n_g ; m2_new = m2 + S2 - (S1/n_g)*S1 -> smem mn/rs
//   Phase B (norm): 8 groups x 64 lanes re-read the bin's rows (L2 hits),
//     out = (x - mn)*rs with stats from smem, streaming stores.
// ---------------------------------------------------------------------------
__global__ void __launch_bounds__(2 * P2) k_fused(const float* __restrict__ patches,
                                                  const float* __restrict__ n_in,
                                                  const float* __restrict__ mean_in,
                                                  const float* __restrict__ m2_in,
                                                  float* __restrict__ out) {
    int bin  = blockIdx.x;
    int tid  = threadIdx.x;
    int half = tid >> 8;                 // 0 or 1
    int p    = tid & (P2 - 1);           // 0..255

    // 16B-aligned stat arrays (Phase B reads them as float4)
    __shared__ __align__(16) float s_mn[P2];
    __shared__ __align__(16) float s_rs[P2];
    __shared__ __align__(16) float s_s1[P2];
    __shared__ __align__(16) float s_s2[P2];
    __shared__ int   s_tok[MAXB];
    __shared__ int   s_cnt;

    if (tid == 0) s_cnt = min(g_bincount[bin], MAXB);
    __syncthreads();
    int cnt = s_cnt;
    if (cnt == 0) return;                // empty bin: nothing to normalize
    for (int i = tid; i < cnt; i += 2 * P2) s_tok[i] = g_binlist[bin * MAXB + i];
    __syncthreads();

    // ---------------- Phase A: stats ----------------
    float mo = mean_in[(size_t)bin * P2 + p];
    float s1 = 0.f, s2 = 0.f;
    const float c3 = 1.0f / 3.0f;

    int i = half;
    for (; i + 6 < cnt; i += 8) {        // 4 tokens/half -> 12 loads in flight
        const float* b0 = patches + (size_t)s_tok[i]     * DD;
        const float* b1 = patches + (size_t)s_tok[i + 2] * DD;
        const float* b2 = patches + (size_t)s_tok[i + 4] * DD;
        const float* b3 = patches + (size_t)s_tok[i + 6] * DD;
        float x00 = b0[p], x01 = b0[p + 256], x02 = b0[p + 512];
        float x10 = b1[p], x11 = b1[p + 256], x12 = b1[p + 512];
        float x20 = b2[p], x21 = b2[p + 256], x22 = b2[p + 512];
        float x30 = b3[p], x31 = b3[p + 256], x32 = b3[p + 512];
        float a0 = (x00 + x01 + x02) * c3 - mo;
        float a1 = (x10 + x11 + x12) * c3 - mo;
        float a2 = (x20 + x21 + x22) * c3 - mo;
        float a3 = (x30 + x31 + x32) * c3 - mo;
        s1 += a0; s2 += a0 * a0;
        s1 += a1; s2 += a1 * a1;
        s1 += a2; s2 += a2 * a2;
        s1 += a3; s2 += a3 * a3;
    }
    for (; i < cnt; i += 2) {
        const float* b0 = patches + (size_t)s_tok[i] * DD;
        float a0 = (b0[p] + b0[p + 256] + b0[p + 512]) * c3 - mo;
        s1 += a0; s2 += a0 * a0;
    }

    if (half == 1) { s_s1[p] = s1; s_s2[p] = s2; }
    __syncthreads();
    if (half == 0) {
        s1 += s_s1[p];
        s2 += s_s2[p];

        float nn  = n_in[bin] + (float)cnt;
        float ng  = fmaxf(nn, 1.0f);
        float u   = s1 / ng;
        float mnv = mo + u;
        float m2v = m2_in[(size_t)bin * P2 + p] + (s2 - u * s1);
        float var = (nn < 2.0f) ? 1.0f : (m2v / ng);

        s_mn[p] = mnv;
        s_rs[p] = 1.0f / (sqrtf(var) + EPSV);
    }
    __syncthreads();

    // ---------------- Phase B: normalize ----------------
    int grp  = tid >> 6;                 // 0..7 token groups
    int lane = tid & 63;                 // owns p = 4*lane .. 4*lane+3
    float4 mn = ((const float4*)s_mn)[lane];
    float4 rs = ((const float4*)s_rs)[lane];

    for (int j = grp; j < cnt; j += 8) {
        int t = s_tok[j];
        const float4* xr   = (const float4*)(patches + (size_t)t * DD);
        float4*       orow = (float4*)(out + (size_t)t * DD);

        float4 x0 = xr[lane];            // L2 hits (just streamed in Phase A)
        float4 x1 = xr[lane + 64];
        float4 x2 = xr[lane + 128];

        float4 o0, o1, o2;
        o0.x = (x0.x - mn.x) * rs.x; o0.y = (x0.y - mn.y) * rs.y;
        o0.z = (x0.z - mn.z) * rs.z; o0.w = (x0.w - mn.w) * rs.w;
        o1.x = (x1.x - mn.x) * rs.x; o1.y = (x1.y - mn.y) * rs.y;
        o1.z = (x1.z - mn.z) * rs.z; o1.w = (x1.w - mn.w) * rs.w;
        o2.x = (x2.x - mn.x) * rs.x; o2.y = (x2.y - mn.y) * rs.y;
        o2.z = (x2.z - mn.z) * rs.z; o2.w = (x2.w - mn.w) * rs.w;

        __stcs(&orow[lane],       o0);
        __stcs(&orow[lane + 64],  o1);
        __stcs(&orow[lane + 128], o2);
    }
}

// ---------------------------------------------------------------------------
extern "C" void kernel_launch(void* const* d_in, const int* in_sizes, int n_in,
                              void* d_out, int out_size) {
    const float* patches = (const float*)d_in[0];
    const int*   pos_h   = (const int*)d_in[1];
    const int*   pos_w   = (const int*)d_in[2];
    const int*   mask    = (const int*)d_in[3];    // bool widened to int32
    const float* n_in0   = (const float*)d_in[4];
    const float* mean_in = (const float*)d_in[5];
    const float* m2_in   = (const float*)d_in[6];
    float*       out     = (float*)d_out;

    k_zero    <<<(HWB + 255) / 256, 256>>>();
    k_bin     <<<(NTOK + 255) / 256, 256>>>(pos_h, pos_w, mask);
    k_maskzero<<<NTOK / 4, 256>>>(mask, out);
    k_fused   <<<HWB, 2 * P2>>>(patches, n_in0, mean_in, m2_in, out);
}

// round 12
// speedup vs baseline: 1.0311x; 1.0311x over previous
#include <cuda_runtime.h>
#include <math.h>

#define BB 32
#define SS 1024
#define NTOK (BB*SS)      // 32768 tokens
#define HH 32
#define WW 32
#define HWB (HH*WW)       // 1024 bins
#define P2 256
#define CC 3
#define DD (CC*P2)        // 768
#define MAXB 192
#define NGRP 8            // token groups per fused block
#define EPSV 1e-6f

// ---- scratch (device globals; no allocation) ----
__device__ int g_bincount[HWB];
__device__ int g_binlist[HWB * MAXB];   // 768 KB

// ---------------------------------------------------------------------------
// K0: zero bin counters AND zero output rows of masked tokens.
//     grid = NTOK/4 blocks x 256 threads (64 lanes per token).
// ---------------------------------------------------------------------------
__global__ void __launch_bounds__(256) k_prep(const int* __restrict__ mask,
                                              float* __restrict__ out) {
    int gt = blockIdx.x * 256 + threadIdx.x;
    if (gt < HWB) g_bincount[gt] = 0;

    int t = blockIdx.x * 4 + (threadIdx.x >> 6);
    int lane = threadIdx.x & 63;
    if (mask[t] == 0) return;
    float4* orow = (float4*)(out + (size_t)t * DD);
    float4 z = make_float4(0.f, 0.f, 0.f, 0.f);
    __stcs(&orow[lane], z);
    __stcs(&orow[lane + 64], z);
    __stcs(&orow[lane + 128], z);
}

// ---------------------------------------------------------------------------
// K1: bin valid tokens by flat grid index pf (mask is int32; nonzero = pad)
// ---------------------------------------------------------------------------
__global__ void k_bin(const int* __restrict__ pos_h,
                      const int* __restrict__ pos_w,
                      const int* __restrict__ mask) {
    int t = blockIdx.x * blockDim.x + threadIdx.x;
    if (t >= NTOK) return;
    if (mask[t] != 0) return;
    int pf = pos_h[t] * WW + pos_w[t];
    int idx = atomicAdd(&g_bincount[pf], 1);
    if (idx < MAXB) g_binlist[pf * MAXB + idx] = t;
}

// ---------------------------------------------------------------------------
// K2: FUSED per-bin stats + normalize. One 512-thread block per bin,
//     organized as NGRP=8 groups x 64 lanes; lane l owns columns 4l..4l+3.
//   Phase A: group g sums tokens g, g+8, ... with float4 loads:
//     a = xbar - mean_old ; S1 += a ; S2 += a*a  -> smem partials
//   Reduce: first 256 threads combine 8 partials, compute
//     mean_new = mo + S1/n_g ; m2_new = m2 + S2 - (S1/n_g)*S1 -> s_mn, s_rs
//   Phase B: same grouping re-reads rows (L2 hits), streaming stores.
// ---------------------------------------------------------------------------
__global__ void __launch_bounds__(512) k_fused(const float* __restrict__ patches,
                                               const float* __restrict__ n_in,
                                               const float* __restrict__ mean_in,
                                               const float* __restrict__ m2_in,
                                               float* __restrict__ out) {
    int bin  = blockIdx.x;
    int tid  = threadIdx.x;
    int grp  = tid >> 6;                 // 0..7
    int lane = tid & 63;                 // owns p = 4*lane .. 4*lane+3

    __shared__ __align__(16) float s_ps1[NGRP * P2];   // 8 KB
    __shared__ __align__(16) float s_ps2[NGRP * P2];   // 8 KB
    __shared__ __align__(16) float s_mn[P2];
    __shared__ __align__(16) float s_rs[P2];
    __shared__ int s_tok[MAXB];
    __shared__ int s_cnt;

    if (tid == 0) s_cnt = min(g_bincount[bin], MAXB);
    __syncthreads();
    int cnt = s_cnt;
    if (cnt == 0) return;
    for (int i = tid; i < cnt; i += 512) s_tok[i] = g_binlist[bin * MAXB + i];
    __syncthreads();

    // ---------------- Phase A: partial sums (float4, 8-way token split) ----
    const float c3 = 1.0f / 3.0f;
    float4 mo = ((const float4*)(mean_in + (size_t)bin * P2))[lane];
    float4 s1 = make_float4(0.f, 0.f, 0.f, 0.f);
    float4 s2 = make_float4(0.f, 0.f, 0.f, 0.f);

    int j = grp;
    for (; j + NGRP < cnt; j += 2 * NGRP) {   // 2 tokens -> 6 loads in flight
        const float4* xa = (const float4*)(patches + (size_t)s_tok[j]        * DD);
        const float4* xb = (const float4*)(patches + (size_t)s_tok[j + NGRP] * DD);
        float4 a0 = xa[lane], a1 = xa[lane + 64], a2 = xa[lane + 128];
        float4 b0 = xb[lane], b1 = xb[lane + 64], b2 = xb[lane + 128];
        float4 aa, bb;
        aa.x = (a0.x + a1.x + a2.x) * c3 - mo.x;
        aa.y = (a0.y + a1.y + a2.y) * c3 - mo.y;
        aa.z = (a0.z + a1.z + a2.z) * c3 - mo.z;
        aa.w = (a0.w + a1.w + a2.w) * c3 - mo.w;
        bb.x = (b0.x + b1.x + b2.x) * c3 - mo.x;
        bb.y = (b0.y + b1.y + b2.y) * c3 - mo.y;
        bb.z = (b0.z + b1.z + b2.z) * c3 - mo.z;
        bb.w = (b0.w + b1.w + b2.w) * c3 - mo.w;
        s1.x += aa.x + bb.x; s1.y += aa.y + bb.y;
        s1.z += aa.z + bb.z; s1.w += aa.w + bb.w;
        s2.x += aa.x * aa.x + bb.x * bb.x; s2.y += aa.y * aa.y + bb.y * bb.y;
        s2.z += aa.z * aa.z + bb.z * bb.z; s2.w += aa.w * aa.w + bb.w * bb.w;
    }
    if (j < cnt) {
        const float4* xa = (const float4*)(patches + (size_t)s_tok[j] * DD);
        float4 a0 = xa[lane], a1 = xa[lane + 64], a2 = xa[lane + 128];
        float4 aa;
        aa.x = (a0.x + a1.x + a2.x) * c3 - mo.x;
        aa.y = (a0.y + a1.y + a2.y) * c3 - mo.y;
        aa.z = (a0.z + a1.z + a2.z) * c3 - mo.z;
        aa.w = (a0.w + a1.w + a2.w) * c3 - mo.w;
        s1.x += aa.x; s1.y += aa.y; s1.z += aa.z; s1.w += aa.w;
        s2.x += aa.x * aa.x; s2.y += aa.y * aa.y;
        s2.z += aa.z * aa.z; s2.w += aa.w * aa.w;
    }
    ((float4*)(s_ps1 + grp * P2))[lane] = s1;
    ((float4*)(s_ps2 + grp * P2))[lane] = s2;
    __syncthreads();

    // ---------------- Reduce + finalize (first 256 threads, p = tid) -------
    if (tid < P2) {
        int p = tid;
        float t1 = 0.f, t2 = 0.f;
#pragma unroll
        for (int g = 0; g < NGRP; g++) {
            t1 += s_ps1[g * P2 + p];
            t2 += s_ps2[g * P2 + p];
        }
        float nn  = n_in[bin] + (float)cnt;
        float ng  = fmaxf(nn, 1.0f);
        float u   = t1 / ng;
        float mop = mean_in[(size_t)bin * P2 + p];
        float m2v = m2_in[(size_t)bin * P2 + p] + (t2 - u * t1);
        float var = (nn < 2.0f) ? 1.0f : (m2v / ng);
        s_mn[p] = mop + u;
        s_rs[p] = 1.0f / (sqrtf(var) + EPSV);
    }
    __syncthreads();

    // ---------------- Phase B: normalize ----------------
    float4 mn = ((const float4*)s_mn)[lane];
    float4 rs = ((const float4*)s_rs)[lane];

    for (int i = grp; i < cnt; i += NGRP) {
        int t = s_tok[i];
        const float4* xr   = (const float4*)(patches + (size_t)t * DD);
        float4*       orow = (float4*)(out + (size_t)t * DD);

        float4 x0 = xr[lane];            // L2 hits (streamed in Phase A)
        float4 x1 = xr[lane + 64];
        float4 x2 = xr[lane + 128];

        float4 o0, o1, o2;
        o0.x = (x0.x - mn.x) * rs.x; o0.y = (x0.y - mn.y) * rs.y;
        o0.z = (x0.z - mn.z) * rs.z; o0.w = (x0.w - mn.w) * rs.w;
        o1.x = (x1.x - mn.x) * rs.x; o1.y = (x1.y - mn.y) * rs.y;
        o1.z = (x1.z - mn.z) * rs.z; o1.w = (x1.w - mn.w) * rs.w;
        o2.x = (x2.x - mn.x) * rs.x; o2.y = (x2.y - mn.y) * rs.y;
        o2.z = (x2.z - mn.z) * rs.z; o2.w = (x2.w - mn.w) * rs.w;

        __stcs(&orow[lane],       o0);
        __stcs(&orow[lane + 64],  o1);
        __stcs(&orow[lane + 128], o2);
    }
}

// ---------------------------------------------------------------------------
extern "C" void kernel_launch(void* const* d_in, const int* in_sizes, int n_in,
                              void* d_out, int out_size) {
    const float* patches = (const float*)d_in[0];
    const int*   pos_h   = (const int*)d_in[1];
    const int*   pos_w   = (const int*)d_in[2];
    const int*   mask    = (const int*)d_in[3];    // bool widened to int32
    const float* n_in0   = (const float*)d_in[4];
    const float* mean_in = (const float*)d_in[5];
    const float* m2_in   = (const float*)d_in[6];
    float*       out     = (float*)d_out;

    k_prep <<<NTOK / 4, 256>>>(mask, out);
    k_bin  <<<(NTOK + 255) / 256, 256>>>(pos_h, pos_w, mask);
    k_fused<<<HWB, 512>>>(patches, n_in0, mean_in, m2_in, out);
}